// round 2
// baseline (speedup 1.0000x reference)
#include <cuda_runtime.h>

// ---------------------------------------------------------------------------
// SpectralConv2d (FNO) without FFT: truncated DFT as dense GEMMs.
// B=8, CIN=COUT=64, H=W=256, M1=M2=32.
//
// Forward:  T[b,c,p,q] = sum_{h,w} x[b,c,h,w] e^{-2pi i (pf(p) h + qf(q) w)/256}
//           pf/qf: m<32 -> m, m>=32 -> m+192  (i.e. freqs 0..31 and 224..255)
// Branch x uses T[p, q<32], branch z uses T[p<32, q] (transposed roles).
// Channel mix with w1/w2 (x) and w3/w4 (z) per mode.
// Inverse:  Y[h,k2] = sum_p S[p,k2] e^{+2pi i pf(p) h /256}
//           out[h,w] = (1/65536) [ Re Y[h,0] + sum_{k2=1..31} 2(ReY cos - ImY sin) ]
// ---------------------------------------------------------------------------

namespace {
constexpr int B_    = 8;
constexpr int CIN_  = 64;
constexpr int COUT_ = 64;
constexpr int H_    = 256;
constexpr int W_    = 256;
constexpr int ROWS_ = B_ * CIN_ * H_;        // 131072 (also B*COUT*H)
constexpr int BC_   = B_ * CIN_;             // 512
constexpr int OUTOFF_ = B_ * COUT_ * H_ * W_; // 33554432
}

// ------------------------- static device scratch ---------------------------
__device__ float  g_Fw[256 * 128];      // [w][2q]=cos, [2q+1]=-sin  (forward, W axis)
__device__ float2 g_Fc[64 * 256];       // [p][h] = (cos, -sin)      (forward, H axis)
__device__ float2 g_Gi[64 * 256];       // [p][h] = (cos, +sin)      (inverse)
__device__ float  g_Cm[64 * 256];       // [j][w] inverse-stage-2 coefficients
__device__ float2 g_t1[ROWS_ * 64];     // tmp after F1: [(bc*256+h)][q]
__device__ float2 g_T [BC_ * 64 * 64];  // [(b*64+ci)][p][q]
__device__ float2 g_Sx[512 * 64 * 32];  // [(b*64+co)][p][k2]
__device__ float2 g_Sz[512 * 64 * 32];
__device__ float  g_Yx[ROWS_ * 64];     // [(bco*256+h)][2k2 | 2k2+1]
__device__ float  g_Yz[ROWS_ * 64];

// ------------------------------ table init --------------------------------
__global__ void init_tables_k() {
    int t = blockIdx.x * blockDim.x + threadIdx.x;
    if (t >= 64 * 256) return;
    int m = t >> 8;          // 0..63 (mode index)
    int n = t & 255;         // 0..255 (spatial index)
    int mf = (m < 32) ? m : m + 192;
    int k = (mf * n) & 255;  // exact phase reduction
    float s, c;
    sincospif((float)k * (1.0f / 128.0f), &s, &c);   // angle = 2*pi*k/256
    g_Fw[n * 128 + 2 * m]     = c;
    g_Fw[n * 128 + 2 * m + 1] = -s;
    g_Fc[m * 256 + n] = make_float2(c, -s);
    g_Gi[m * 256 + n] = make_float2(c,  s);

    // inverse stage-2 coefficient table (j in 0..63, w = n)
    int k2 = m >> 1;
    int kk = (k2 * n) & 255;
    float s2, c2;
    sincospif((float)kk * (1.0f / 128.0f), &s2, &c2);
    const float sc = 1.0f / 65536.0f;
    float v;
    if ((m & 1) == 0) v = (k2 == 0) ? sc : 2.0f * sc * c2;
    else              v = (k2 == 0) ? 0.0f : -2.0f * sc * s2;
    g_Cm[m * 256 + n] = v;
}

// ------------------------- generic fp32 tiled GEMM -------------------------
// C[M,N] = A[M,K] * B[K,N].  BM=64, BN=128, BK=16, thread tile 4x8, 256 thr.
__global__ __launch_bounds__(256)
void sgemm_k(const float* __restrict__ A, const float* __restrict__ Bm,
             float* __restrict__ Cc, int K, int lda, int ldb, int ldc) {
    __shared__ float As[16][64];
    __shared__ float Bs[16][128];
    int t  = threadIdx.x;
    int tx = t & 15, ty = t >> 4;
    int m0 = blockIdx.x * 64;
    int n0 = blockIdx.y * 128;
    float acc[4][8];
#pragma unroll
    for (int i = 0; i < 4; i++)
#pragma unroll
        for (int j = 0; j < 8; j++) acc[i][j] = 0.0f;

    int ar = t >> 2, ac = (t & 3) * 4;
    for (int k0 = 0; k0 < K; k0 += 16) {
        float4 av = *(const float4*)&A[(size_t)(m0 + ar) * lda + k0 + ac];
        As[ac + 0][ar] = av.x; As[ac + 1][ar] = av.y;
        As[ac + 2][ar] = av.z; As[ac + 3][ar] = av.w;
#pragma unroll
        for (int i = 0; i < 2; i++) {
            int lin = i * 256 + t;           // 512 float4 in 16x128 tile
            int br = lin >> 5, bc4 = (lin & 31) * 4;
            *(float4*)&Bs[br][bc4] = *(const float4*)&Bm[(size_t)(k0 + br) * ldb + n0 + bc4];
        }
        __syncthreads();
#pragma unroll
        for (int k = 0; k < 16; k++) {
            float a[4], b[8];
            *(float4*)a       = *(float4*)&As[k][ty * 4];
            *(float4*)b       = *(float4*)&Bs[k][tx * 8];
            *(float4*)(b + 4) = *(float4*)&Bs[k][tx * 8 + 4];
#pragma unroll
            for (int i = 0; i < 4; i++)
#pragma unroll
                for (int j = 0; j < 8; j++) acc[i][j] = fmaf(a[i], b[j], acc[i][j]);
        }
        __syncthreads();
    }
#pragma unroll
    for (int i = 0; i < 4; i++) {
        float* cr = &Cc[(size_t)(m0 + ty * 4 + i) * ldc + n0 + tx * 8];
        *(float4*)cr       = make_float4(acc[i][0], acc[i][1], acc[i][2], acc[i][3]);
        *(float4*)(cr + 4) = make_float4(acc[i][4], acc[i][5], acc[i][6], acc[i][7]);
    }
}

// ------------------- F2: per-(b,c) complex GEMM over h ---------------------
// T[bc][p][q] = sum_h Fc[p][h] * t1[bc*256+h][q]
__global__ __launch_bounds__(256)
void f2_k() {
    int bc = blockIdx.x;
    const float2* tin  = g_t1 + (size_t)bc * 256 * 64;
    float2*       tout = g_T  + (size_t)bc * 64 * 64;
    __shared__ float2 Fs[64][64];   // [p][hh]
    __shared__ float2 Vs[64][64];   // [hh][q]
    int t = threadIdx.x;
    int txq = t & 15, typ = t >> 4;
    float2 acc[4][4];
#pragma unroll
    for (int i = 0; i < 4; i++)
#pragma unroll
        for (int j = 0; j < 4; j++) acc[i][j] = make_float2(0.f, 0.f);

    for (int h0 = 0; h0 < 256; h0 += 64) {
#pragma unroll
        for (int i = 0; i < 16; i++) {
            int lin = i * 256 + t;
            int hh = lin >> 6, q = lin & 63;
            Vs[hh][q] = tin[(size_t)(h0 + hh) * 64 + q];
        }
#pragma unroll
        for (int i = 0; i < 16; i++) {
            int lin = i * 256 + t;
            int p = lin >> 6, hh = lin & 63;
            Fs[p][hh] = g_Fc[p * 256 + h0 + hh];
        }
        __syncthreads();
        for (int hh = 0; hh < 64; hh++) {
            float2 e[4], v[4];
#pragma unroll
            for (int i = 0; i < 4; i++) e[i] = Fs[typ * 4 + i][hh];
#pragma unroll
            for (int j = 0; j < 4; j++) v[j] = Vs[hh][txq * 4 + j];
#pragma unroll
            for (int i = 0; i < 4; i++)
#pragma unroll
                for (int j = 0; j < 4; j++) {
                    acc[i][j].x = fmaf(e[i].x, v[j].x, fmaf(-e[i].y, v[j].y, acc[i][j].x));
                    acc[i][j].y = fmaf(e[i].x, v[j].y, fmaf( e[i].y, v[j].x, acc[i][j].y));
                }
        }
        __syncthreads();
    }
#pragma unroll
    for (int i = 0; i < 4; i++)
#pragma unroll
        for (int j = 0; j < 4; j++)
            tout[(size_t)(typ * 4 + i) * 64 + txq * 4 + j] = acc[i][j];
}

// -------------------- channel mix (both branches) --------------------------
// grid (64, 2): x = mode-row p (x-branch: h-freq; z-branch: w-freq k1), y = branch
__global__ __launch_bounds__(512)
void mix_k(const float* __restrict__ w1r, const float* __restrict__ w1i,
           const float* __restrict__ w2r, const float* __restrict__ w2i,
           const float* __restrict__ w3r, const float* __restrict__ w3i,
           const float* __restrict__ w4r, const float* __restrict__ w4i) {
    int p  = blockIdx.x;
    int zb = blockIdx.y;
    int pm = p & 31;
    const float *wr, *wi;
    if (!zb) { wr = (p < 32) ? w1r : w2r; wi = (p < 32) ? w1i : w2i; }
    else     { wr = (p < 32) ? w3r : w4r; wi = (p < 32) ? w3i : w4i; }
    float2* Sout = zb ? g_Sz : g_Sx;

    int t = threadIdx.x;
    int lane = t & 31;         // k2
    int warp = t >> 5;         // 16 warps -> co = warp*4 + j
    __shared__ float2 Ts[16][8][32];
    float2 acc[8][4];
#pragma unroll
    for (int b = 0; b < 8; b++)
#pragma unroll
        for (int j = 0; j < 4; j++) acc[b][j] = make_float2(0.f, 0.f);

    for (int cc = 0; cc < 64; cc += 16) {
#pragma unroll
        for (int i = 0; i < 8; i++) {
            int lin = i * 512 + t;               // [ci_l(16)][b(8)][q(32)]
            int ci_l = lin >> 8;
            int b = (lin >> 5) & 7;
            int q = lin & 31;
            int ci = cc + ci_l;
            size_t idx;
            if (!zb) idx = ((size_t)(b * 64 + ci) * 64 + p) * 64 + q;
            else     idx = ((size_t)(b * 64 + ci) * 64 + q) * 64 + p;
            Ts[ci_l][b][q] = g_T[idx];
        }
        __syncthreads();
        for (int ci_l = 0; ci_l < 16; ci_l++) {
            int ci = cc + ci_l;
            float wr4[4], wi4[4];
#pragma unroll
            for (int j = 0; j < 4; j++) {
                int co = warp * 4 + j;
                size_t off = ((size_t)(ci * 64 + co) * 32 + pm) * 32 + lane;
                wr4[j] = wr[off];
                wi4[j] = wi[off];
            }
#pragma unroll
            for (int b = 0; b < 8; b++) {
                float2 tv = Ts[ci_l][b][lane];
#pragma unroll
                for (int j = 0; j < 4; j++) {
                    acc[b][j].x = fmaf(tv.x, wr4[j], fmaf(-tv.y, wi4[j], acc[b][j].x));
                    acc[b][j].y = fmaf(tv.x, wi4[j], fmaf( tv.y, wr4[j], acc[b][j].y));
                }
            }
        }
        __syncthreads();
    }
#pragma unroll
    for (int b = 0; b < 8; b++)
#pragma unroll
        for (int j = 0; j < 4; j++) {
            int co = warp * 4 + j;
            Sout[((size_t)(b * 64 + co) * 64 + p) * 32 + lane] = acc[b][j];
        }
}

// ---------------- I1: per-(b,co) complex GEMM modes -> h -------------------
// Y[bco][h][k2] = sum_p S[p][k2] * Gi[p][h]
__global__ __launch_bounds__(256)
void i1_k() {
    int bc = blockIdx.x;
    const float2* Sb = (blockIdx.y ? g_Sz : g_Sx) + (size_t)bc * 2048;
    float2* Yb = (float2*)(blockIdx.y ? g_Yz : g_Yx) + (size_t)bc * 256 * 32;
    __shared__ float2 Ss[64][32];
    __shared__ float2 Gs[64][64];
    int t = threadIdx.x;
#pragma unroll
    for (int i = 0; i < 8; i++) {
        int lin = i * 256 + t;
        Ss[lin >> 5][lin & 31] = Sb[lin];
    }
    int k2b = (t & 7) * 4;
    int hb  = (t >> 3) * 2;
    for (int h0 = 0; h0 < 256; h0 += 64) {
        __syncthreads();
#pragma unroll
        for (int i = 0; i < 16; i++) {
            int lin = i * 256 + t;
            int p = lin >> 6, hl = lin & 63;
            Gs[p][hl] = g_Gi[p * 256 + h0 + hl];
        }
        __syncthreads();
        float2 acc[2][4];
#pragma unroll
        for (int hi = 0; hi < 2; hi++)
#pragma unroll
            for (int j = 0; j < 4; j++) acc[hi][j] = make_float2(0.f, 0.f);
        for (int pp = 0; pp < 64; pp++) {
            float2 g0 = Gs[pp][hb], g1 = Gs[pp][hb + 1];
#pragma unroll
            for (int j = 0; j < 4; j++) {
                float2 sv = Ss[pp][k2b + j];
                acc[0][j].x = fmaf(g0.x, sv.x, fmaf(-g0.y, sv.y, acc[0][j].x));
                acc[0][j].y = fmaf(g0.x, sv.y, fmaf( g0.y, sv.x, acc[0][j].y));
                acc[1][j].x = fmaf(g1.x, sv.x, fmaf(-g1.y, sv.y, acc[1][j].x));
                acc[1][j].y = fmaf(g1.x, sv.y, fmaf( g1.y, sv.x, acc[1][j].y));
            }
        }
#pragma unroll
        for (int hi = 0; hi < 2; hi++)
#pragma unroll
            for (int j = 0; j < 4; j++)
                Yb[(size_t)(h0 + hb + hi) * 32 + k2b + j] = acc[hi][j];
    }
}

// ------------------------------- launcher ----------------------------------
extern "C" void kernel_launch(void* const* d_in, const int* in_sizes, int n_in,
                              void* d_out, int out_size) {
    const float* x   = (const float*)d_in[0];
    const float* w1r = (const float*)d_in[1];
    const float* w1i = (const float*)d_in[2];
    const float* w2r = (const float*)d_in[3];
    const float* w2i = (const float*)d_in[4];
    const float* w3r = (const float*)d_in[5];
    const float* w3i = (const float*)d_in[6];
    const float* w4r = (const float*)d_in[7];
    const float* w4i = (const float*)d_in[8];
    float* out = (float*)d_out;

    float *pFw, *pCm, *pT1, *pYx, *pYz;
    cudaGetSymbolAddress((void**)&pFw, g_Fw);
    cudaGetSymbolAddress((void**)&pCm, g_Cm);
    cudaGetSymbolAddress((void**)&pT1, g_t1);
    cudaGetSymbolAddress((void**)&pYx, g_Yx);
    cudaGetSymbolAddress((void**)&pYz, g_Yz);

    init_tables_k<<<64, 256>>>();

    // F1: (ROWS x 256) * (256 x 128) -> t1
    sgemm_k<<<dim3(ROWS_ / 64, 1), 256>>>(x, pFw, pT1, 256, 256, 128, 128);

    // F2: per-(b,c) complex transform over h -> T
    f2_k<<<BC_, 256>>>();

    // channel mix, both branches
    mix_k<<<dim3(64, 2), 512>>>(w1r, w1i, w2r, w2i, w3r, w3i, w4r, w4i);

    // I1: modes -> h, both branches
    i1_k<<<dim3(512, 2), 256>>>();

    // I2: (ROWS x 64) * (64 x 256) -> outputs
    sgemm_k<<<dim3(ROWS_ / 64, 2), 256>>>(pYx, pCm, out,           64, 64, 256, 256);
    sgemm_k<<<dim3(ROWS_ / 64, 2), 256>>>(pYz, pCm, out + OUTOFF_, 64, 64, 256, 256);
}

// round 4
// speedup vs baseline: 1.9063x; 1.9063x over previous
#include <cuda_runtime.h>
#include <cstdint>

// ---------------------------------------------------------------------------
// SpectralConv2d (FNO) without FFT: truncated DFT as dense GEMMs.
// F1 (x @ Fw^T) and I2 (Y @ Cm^T) on mma.sync tf32 (compute_103-safe HMMA).
// F2 / mix / I1 remain exact fp32 FFMA.
// ---------------------------------------------------------------------------

namespace {
constexpr int ROWS_   = 131072;      // B*C*H
constexpr int BC_     = 512;         // B*C
constexpr int OUTOFF_ = 33554432;    // B*COUT*H*W
}

// ------------------------- static device scratch ---------------------------
__device__ __align__(16) float2 g_Fc [64 * 256];   // fwd H-axis (cos,-sin)
__device__ __align__(16) float2 g_Gi [64 * 256];   // inv H-axis (cos,+sin)
__device__ __align__(16) float  g_Bt [128 * 256];  // F1 B^T: [n][k=w], tf32-rounded
__device__ __align__(16) float  g_CmT[256 * 64];   // I2 B^T: [n=w][k=j], tf32-rounded
__device__ __align__(16) float2 g_t1 [ROWS_ * 64]; // after F1
__device__ __align__(16) float2 g_T  [BC_ * 64 * 64];
__device__ __align__(16) float2 g_Sx [512 * 64 * 32];
__device__ __align__(16) float2 g_Sz [512 * 64 * 32];
__device__ __align__(16) float  g_Yx [ROWS_ * 64];
__device__ __align__(16) float  g_Yz [ROWS_ * 64];

// ------------------------------ helpers ------------------------------------
__device__ __forceinline__ float to_tf32(float x) {
    float r; asm("cvt.rna.tf32.f32 %0, %1;" : "=f"(r) : "f"(x)); return r;
}
#define CP_ASYNC16(dst_u32, src_ptr) \
    asm volatile("cp.async.cg.shared.global [%0], [%1], 16;" :: "r"(dst_u32), "l"(src_ptr))
#define CP_COMMIT() asm volatile("cp.async.commit_group;")
#define CP_WAIT(n)  asm volatile("cp.async.wait_group %0;" :: "n"(n))

#define MMA_TF32(d0,d1,d2,d3, a0,a1,a2,a3, b0,b1)                                   \
    asm volatile("mma.sync.aligned.m16n8k8.row.col.f32.tf32.tf32.f32 "              \
        "{%0,%1,%2,%3}, {%4,%5,%6,%7}, {%8,%9}, {%0,%1,%2,%3};"                     \
        : "+f"(d0), "+f"(d1), "+f"(d2), "+f"(d3)                                    \
        : "r"(a0), "r"(a1), "r"(a2), "r"(a3), "r"(b0), "r"(b1))

// ------------------------------ table init --------------------------------
__global__ void init_tables_k() {
    int t = blockIdx.x * blockDim.x + threadIdx.x;
    if (t >= 64 * 256) return;
    int m = t >> 8, n = t & 255;
    int mf = (m < 32) ? m : m + 192;
    int k = (mf * n) & 255;
    float s, c;
    sincospif((float)k * (1.0f / 128.0f), &s, &c);
    g_Fc[m * 256 + n] = make_float2(c, -s);
    g_Gi[m * 256 + n] = make_float2(c,  s);
    g_Bt[(2 * m) * 256 + n]     = to_tf32(c);
    g_Bt[(2 * m + 1) * 256 + n] = to_tf32(-s);

    int k2 = m >> 1;
    int kk = (k2 * n) & 255;
    float s2, c2;
    sincospif((float)kk * (1.0f / 128.0f), &s2, &c2);
    const float sc = 1.0f / 65536.0f;
    float v;
    if ((m & 1) == 0) v = (k2 == 0) ? sc : 2.0f * sc * c2;
    else              v = (k2 == 0) ? 0.0f : -2.0f * sc * s2;
    g_CmT[n * 64 + m] = to_tf32(v);
}

// -------------------- tf32 mma.sync GEMM -----------------------------------
// C[M,N] = A[M,K] * Bt[N,K]^T.  BM=BN=128, BK=16, 8 warps (2x4), 64x32/warp.
// A row-major lda=K; Bt row-major ldb=K; C row-major ldc.
__global__ __launch_bounds__(256)
void gemm_tc(const float* __restrict__ A, const float* __restrict__ Bt,
             float* __restrict__ C, int K, int ldc) {
    __shared__ float As[2][128][20];
    __shared__ float Bs[2][128][20];
    int t = threadIdx.x;
    int warp = t >> 5, lane = t & 31;
    int gid = lane >> 2, tig = lane & 3;
    int wm = warp & 1, wn = warp >> 1;           // 2 x 4 warp grid
    size_t m0 = (size_t)blockIdx.x * 128;
    size_t n0 = (size_t)blockIdx.y * 128;
    int nK = K >> 4;

    float acc[4][4][4];
#pragma unroll
    for (int mi = 0; mi < 4; mi++)
#pragma unroll
        for (int ni = 0; ni < 4; ni++)
#pragma unroll
            for (int r = 0; r < 4; r++) acc[mi][ni][r] = 0.0f;

    int lr  = t >> 2;            // 0..63 row (2 iters -> 128)
    int lc4 = (t & 3) * 4;       // 0,4,8,12

    auto load_stage = [&](int s, int k0) {
#pragma unroll
        for (int i = 0; i < 2; i++) {
            int r = i * 64 + lr;
            uint32_t da = (uint32_t)__cvta_generic_to_shared(&As[s][r][lc4]);
            CP_ASYNC16(da, &A[(m0 + r) * K + k0 + lc4]);
            uint32_t db = (uint32_t)__cvta_generic_to_shared(&Bs[s][r][lc4]);
            CP_ASYNC16(db, &Bt[(n0 + r) * K + k0 + lc4]);
        }
        CP_COMMIT();
    };

    load_stage(0, 0);
    for (int k0 = 0; k0 < nK; k0++) {
        int s = k0 & 1;
        if (k0 + 1 < nK) { load_stage(s ^ 1, (k0 + 1) << 4); CP_WAIT(1); }
        else             { CP_WAIT(0); }
        __syncthreads();
#pragma unroll
        for (int kk = 0; kk < 16; kk += 8) {
            uint32_t af[4][4], bf[4][2];
#pragma unroll
            for (int mi = 0; mi < 4; mi++) {
                int mr = wm * 64 + mi * 16 + gid;
                af[mi][0] = __float_as_uint(As[s][mr][kk + tig]);
                af[mi][1] = __float_as_uint(As[s][mr + 8][kk + tig]);
                af[mi][2] = __float_as_uint(As[s][mr][kk + tig + 4]);
                af[mi][3] = __float_as_uint(As[s][mr + 8][kk + tig + 4]);
            }
#pragma unroll
            for (int ni = 0; ni < 4; ni++) {
                int nr = wn * 32 + ni * 8 + gid;
                bf[ni][0] = __float_as_uint(Bs[s][nr][kk + tig]);
                bf[ni][1] = __float_as_uint(Bs[s][nr][kk + tig + 4]);
            }
#pragma unroll
            for (int mi = 0; mi < 4; mi++)
#pragma unroll
                for (int ni = 0; ni < 4; ni++)
                    MMA_TF32(acc[mi][ni][0], acc[mi][ni][1], acc[mi][ni][2], acc[mi][ni][3],
                             af[mi][0], af[mi][1], af[mi][2], af[mi][3],
                             bf[ni][0], bf[ni][1]);
        }
        __syncthreads();
    }

#pragma unroll
    for (int mi = 0; mi < 4; mi++) {
        size_t r0 = m0 + wm * 64 + mi * 16 + gid;
#pragma unroll
        for (int ni = 0; ni < 4; ni++) {
            size_t cb = n0 + wn * 32 + ni * 8 + tig * 2;
            *(float2*)&C[r0 * ldc + cb]       = make_float2(acc[mi][ni][0], acc[mi][ni][1]);
            *(float2*)&C[(r0 + 8) * ldc + cb] = make_float2(acc[mi][ni][2], acc[mi][ni][3]);
        }
    }
}

// ------------------- F2: per-(b,c) complex GEMM over h ---------------------
__global__ __launch_bounds__(256)
void f2_k() {
    int bc = blockIdx.x;
    const float2* tin  = g_t1 + (size_t)bc * 256 * 64;
    float2*       tout = g_T  + (size_t)bc * 64 * 64;
    __shared__ float2 Fs[64][64];
    __shared__ float2 Vs[64][64];
    int t = threadIdx.x;
    int txq = t & 15, typ = t >> 4;
    float2 acc[4][4];
#pragma unroll
    for (int i = 0; i < 4; i++)
#pragma unroll
        for (int j = 0; j < 4; j++) acc[i][j] = make_float2(0.f, 0.f);

    for (int h0 = 0; h0 < 256; h0 += 64) {
#pragma unroll
        for (int i = 0; i < 16; i++) {
            int lin = i * 256 + t;
            int hh = lin >> 6, q = lin & 63;
            Vs[hh][q] = tin[(size_t)(h0 + hh) * 64 + q];
        }
#pragma unroll
        for (int i = 0; i < 16; i++) {
            int lin = i * 256 + t;
            int p = lin >> 6, hh = lin & 63;
            Fs[p][hh] = g_Fc[p * 256 + h0 + hh];
        }
        __syncthreads();
        for (int hh = 0; hh < 64; hh++) {
            float2 e[4], v[4];
#pragma unroll
            for (int i = 0; i < 4; i++) e[i] = Fs[typ * 4 + i][hh];
#pragma unroll
            for (int j = 0; j < 4; j++) v[j] = Vs[hh][txq * 4 + j];
#pragma unroll
            for (int i = 0; i < 4; i++)
#pragma unroll
                for (int j = 0; j < 4; j++) {
                    acc[i][j].x = fmaf(e[i].x, v[j].x, fmaf(-e[i].y, v[j].y, acc[i][j].x));
                    acc[i][j].y = fmaf(e[i].x, v[j].y, fmaf( e[i].y, v[j].x, acc[i][j].y));
                }
        }
        __syncthreads();
    }
#pragma unroll
    for (int i = 0; i < 4; i++)
#pragma unroll
        for (int j = 0; j < 4; j++)
            tout[(size_t)(typ * 4 + i) * 64 + txq * 4 + j] = acc[i][j];
}

// -------------------- channel mix (both branches) --------------------------
__global__ __launch_bounds__(512)
void mix_k(const float* __restrict__ w1r, const float* __restrict__ w1i,
           const float* __restrict__ w2r, const float* __restrict__ w2i,
           const float* __restrict__ w3r, const float* __restrict__ w3i,
           const float* __restrict__ w4r, const float* __restrict__ w4i) {
    int p  = blockIdx.x;
    int zb = blockIdx.y;
    int pm = p & 31;
    const float *wr, *wi;
    if (!zb) { wr = (p < 32) ? w1r : w2r; wi = (p < 32) ? w1i : w2i; }
    else     { wr = (p < 32) ? w3r : w4r; wi = (p < 32) ? w3i : w4i; }
    float2* Sout = zb ? g_Sz : g_Sx;

    int t = threadIdx.x;
    int lane = t & 31;
    int warp = t >> 5;
    __shared__ float2 Ts[16][8][32];
    float2 acc[8][4];
#pragma unroll
    for (int b = 0; b < 8; b++)
#pragma unroll
        for (int j = 0; j < 4; j++) acc[b][j] = make_float2(0.f, 0.f);

    for (int cc = 0; cc < 64; cc += 16) {
#pragma unroll
        for (int i = 0; i < 8; i++) {
            int lin = i * 512 + t;
            int ci_l = lin >> 8;
            int b = (lin >> 5) & 7;
            int q = lin & 31;
            int ci = cc + ci_l;
            size_t idx;
            if (!zb) idx = ((size_t)(b * 64 + ci) * 64 + p) * 64 + q;
            else     idx = ((size_t)(b * 64 + ci) * 64 + q) * 64 + p;
            Ts[ci_l][b][q] = g_T[idx];
        }
        __syncthreads();
        for (int ci_l = 0; ci_l < 16; ci_l++) {
            int ci = cc + ci_l;
            float wr4[4], wi4[4];
#pragma unroll
            for (int j = 0; j < 4; j++) {
                int co = warp * 4 + j;
                size_t off = ((size_t)(ci * 64 + co) * 32 + pm) * 32 + lane;
                wr4[j] = wr[off];
                wi4[j] = wi[off];
            }
#pragma unroll
            for (int b = 0; b < 8; b++) {
                float2 tv = Ts[ci_l][b][lane];
#pragma unroll
                for (int j = 0; j < 4; j++) {
                    acc[b][j].x = fmaf(tv.x, wr4[j], fmaf(-tv.y, wi4[j], acc[b][j].x));
                    acc[b][j].y = fmaf(tv.x, wi4[j], fmaf( tv.y, wr4[j], acc[b][j].y));
                }
            }
        }
        __syncthreads();
    }
#pragma unroll
    for (int b = 0; b < 8; b++)
#pragma unroll
        for (int j = 0; j < 4; j++) {
            int co = warp * 4 + j;
            Sout[((size_t)(b * 64 + co) * 64 + p) * 32 + lane] = acc[b][j];
        }
}

// ---------------- I1: per-(b,co) complex GEMM modes -> h -------------------
__global__ __launch_bounds__(256)
void i1_k() {
    int bc = blockIdx.x;
    const float2* Sb = (blockIdx.y ? g_Sz : g_Sx) + (size_t)bc * 2048;
    float2* Yb = (float2*)(blockIdx.y ? g_Yz : g_Yx) + (size_t)bc * 256 * 32;
    __shared__ float2 Ss[64][32];
    __shared__ float2 Gs[64][64];
    int t = threadIdx.x;
#pragma unroll
    for (int i = 0; i < 8; i++) {
        int lin = i * 256 + t;
        Ss[lin >> 5][lin & 31] = Sb[lin];
    }
    int k2b = (t & 7) * 4;
    int hb  = (t >> 3) * 2;
    for (int h0 = 0; h0 < 256; h0 += 64) {
        __syncthreads();
#pragma unroll
        for (int i = 0; i < 16; i++) {
            int lin = i * 256 + t;
            int p = lin >> 6, hl = lin & 63;
            Gs[p][hl] = g_Gi[p * 256 + h0 + hl];
        }
        __syncthreads();
        float2 acc[2][4];
#pragma unroll
        for (int hi = 0; hi < 2; hi++)
#pragma unroll
            for (int j = 0; j < 4; j++) acc[hi][j] = make_float2(0.f, 0.f);
        for (int pp = 0; pp < 64; pp++) {
            float2 g0 = Gs[pp][hb], g1 = Gs[pp][hb + 1];
#pragma unroll
            for (int j = 0; j < 4; j++) {
                float2 sv = Ss[pp][k2b + j];
                acc[0][j].x = fmaf(g0.x, sv.x, fmaf(-g0.y, sv.y, acc[0][j].x));
                acc[0][j].y = fmaf(g0.x, sv.y, fmaf( g0.y, sv.x, acc[0][j].y));
                acc[1][j].x = fmaf(g1.x, sv.x, fmaf(-g1.y, sv.y, acc[1][j].x));
                acc[1][j].y = fmaf(g1.x, sv.y, fmaf( g1.y, sv.x, acc[1][j].y));
            }
        }
#pragma unroll
        for (int hi = 0; hi < 2; hi++)
#pragma unroll
            for (int j = 0; j < 4; j++)
                Yb[(size_t)(h0 + hb + hi) * 32 + k2b + j] = acc[hi][j];
    }
}

// ------------------------------- launcher ----------------------------------
extern "C" void kernel_launch(void* const* d_in, const int* in_sizes, int n_in,
                              void* d_out, int out_size) {
    const float* x   = (const float*)d_in[0];
    const float* w1r = (const float*)d_in[1];
    const float* w1i = (const float*)d_in[2];
    const float* w2r = (const float*)d_in[3];
    const float* w2i = (const float*)d_in[4];
    const float* w3r = (const float*)d_in[5];
    const float* w3i = (const float*)d_in[6];
    const float* w4r = (const float*)d_in[7];
    const float* w4i = (const float*)d_in[8];
    float* out = (float*)d_out;

    float *pBt, *pCmT, *pT1, *pYx, *pYz;
    cudaGetSymbolAddress((void**)&pBt,  g_Bt);
    cudaGetSymbolAddress((void**)&pCmT, g_CmT);
    cudaGetSymbolAddress((void**)&pT1,  g_t1);
    cudaGetSymbolAddress((void**)&pYx,  g_Yx);
    cudaGetSymbolAddress((void**)&pYz,  g_Yz);

    init_tables_k<<<64, 256>>>();

    // F1: (131072 x 256) * (128 x 256)^T -> t1 (tf32 tensor cores)
    gemm_tc<<<dim3(1024, 1), 256>>>(x, pBt, pT1, 256, 128);

    f2_k<<<BC_, 256>>>();
    mix_k<<<dim3(64, 2), 512>>>(w1r, w1i, w2r, w2i, w3r, w3i, w4r, w4i);
    i1_k<<<dim3(512, 2), 256>>>();

    // I2: (131072 x 64) * (256 x 64)^T -> outputs (tf32 tensor cores)
    gemm_tc<<<dim3(1024, 2), 256>>>(pYx, pCmT, out,           64, 256);
    gemm_tc<<<dim3(1024, 2), 256>>>(pYz, pCmT, out + OUTOFF_, 64, 256);
}

// round 5
// speedup vs baseline: 2.6075x; 1.3679x over previous
#include <cuda_runtime.h>
#include <cstdint>

// ---------------------------------------------------------------------------
// SpectralConv2d (FNO) without FFT: the whole truncated-DFT pipeline as tf32
// mma.sync GEMMs (compute_103-safe). Only the weight mix stays fp32 FFMA.
//   F1 : t1T[128][131072]   = Bt(128x256)  . x^T            (plain)
//   F2 : T2 [128][32768]    = A2(128x512)  . gather(t1T)^T  (B gathered)
//   mix: fp32 FFMA, reads T2 planes, writes S2 in B-operand layout (tf32)
//   I1 : Y2 [512][16384]x2  = A3(512x128)  . S2^T           (plain)
//   I2 : out[131072][256]x2 = gather(Y2)   . CmT2(256x64)^T (A gathered)
// All tensor-stage inputs rna-rounded to tf32 (tables at init, tensors at the
// write side, x at fragment load) to avoid biased HW truncation.
// ---------------------------------------------------------------------------

namespace {
constexpr int ROWS_   = 131072;      // B*C*H
constexpr int OUTOFF_ = 33554432;    // B*COUT*H*W
}

// ------------------------- static device scratch ---------------------------
__device__ __align__(16) float g_Bt  [128 * 256];        // F1 A: 2q=cos, 2q+1=-sin
__device__ __align__(16) float g_A2  [128 * 512];        // F2 A
__device__ __align__(16) float g_A3  [512 * 128];        // I1 A
__device__ __align__(16) float g_CmT2[256 * 64];         // I2 B (planar k)
__device__ __align__(16) float g_t1T [128 * ROWS_];      // F1 out (64MB)
__device__ __align__(16) float g_T2  [128 * 32768];      // F2 out (16MB)
__device__ __align__(16) float g_S2  [2 * 16384 * 128];  // mix out (16MB)
__device__ __align__(16) float g_Y2  [2 * 512 * 16384];  // I1 out (64MB)

// ------------------------------ helpers ------------------------------------
__device__ __forceinline__ float to_tf32(float x) {
    float r; asm("cvt.rna.tf32.f32 %0, %1;" : "=f"(r) : "f"(x)); return r;
}
#define CP_ASYNC16(dst_u32, src_ptr) \
    asm volatile("cp.async.cg.shared.global [%0], [%1], 16;" :: "r"(dst_u32), "l"(src_ptr))
#define CP_COMMIT() asm volatile("cp.async.commit_group;")
#define CP_WAIT(n)  asm volatile("cp.async.wait_group %0;" :: "n"(n))

#define MMA_TF32(d0,d1,d2,d3, a0,a1,a2,a3, b0,b1)                                   \
    asm volatile("mma.sync.aligned.m16n8k8.row.col.f32.tf32.tf32.f32 "              \
        "{%0,%1,%2,%3}, {%4,%5,%6,%7}, {%8,%9}, {%0,%1,%2,%3};"                     \
        : "+f"(d0), "+f"(d1), "+f"(d2), "+f"(d3)                                    \
        : "r"(a0), "r"(a1), "r"(a2), "r"(a3), "r"(b0), "r"(b1))

// ------------------------------ table init --------------------------------
__global__ void init_tables_k() {
    int t = blockIdx.x * blockDim.x + threadIdx.x;
    if (t >= 64 * 256) return;
    int m = t >> 8, n = t & 255;               // m: mode 0..63, n: spatial 0..255
    int mf = (m < 32) ? m : m + 192;
    int k = (mf * n) & 255;
    float s, c;
    sincospif((float)k * (1.0f / 128.0f), &s, &c);   // theta = 2*pi*mf*n/256
    float tc = to_tf32(c), ts = to_tf32(s), tns = to_tf32(-s);

    // F1 A (q-modes over w):   Re row = cos, Im row = -sin
    g_Bt[(2 * m) * 256 + n]     = tc;
    g_Bt[(2 * m + 1) * 256 + n] = tns;
    // F2 A (p-modes over h):  ReT = cos*Re + sin*Im ; ImT = -sin*Re + cos*Im
    g_A2[(2 * m) * 512 + n]           = tc;
    g_A2[(2 * m) * 512 + 256 + n]     = ts;
    g_A2[(2 * m + 1) * 512 + n]       = tns;
    g_A2[(2 * m + 1) * 512 + 256 + n] = tc;
    // I1 A (h rows over p):   ReY = cos*Re - sin*Im ; ImY = sin*Re + cos*Im
    g_A3[(2 * n) * 128 + m]          = tc;
    g_A3[(2 * n) * 128 + 64 + m]     = tns;
    g_A3[(2 * n + 1) * 128 + m]      = ts;
    g_A3[(2 * n + 1) * 128 + 64 + m] = tc;

    // I2 B, planar: k<32 -> Re coeff (cos), k>=32 -> Im coeff (-sin)
    int k2 = m & 31;
    int kk = (k2 * n) & 255;
    float s2, c2;
    sincospif((float)kk * (1.0f / 128.0f), &s2, &c2);
    const float sc = 1.0f / 65536.0f;
    float v;
    if (m < 32) v = (k2 == 0) ? sc : 2.0f * sc * c2;
    else        v = (k2 == 0) ? 0.0f : -2.0f * sc * s2;
    g_CmT2[n * 64 + m] = to_tf32(v);
}

// -------------------- tf32 mma.sync GEMM (plain A/B) -----------------------
// C[M,N] = A[M,K] * Bt[N,K]^T.  BM=BN=128, BK=16, 8 warps (2x4), 64x32/warp.
template<int CVTB, int CVTC>
__global__ __launch_bounds__(256)
void gemm_tc(const float* __restrict__ A, const float* __restrict__ Bt,
             float* __restrict__ C, int K, int ldc) {
    __shared__ float As[2][128][20];
    __shared__ float Bs[2][128][20];
    int t = threadIdx.x;
    int warp = t >> 5, lane = t & 31;
    int gid = lane >> 2, tig = lane & 3;
    int wm = warp & 1, wn = warp >> 1;
    size_t m0 = (size_t)blockIdx.x * 128;
    size_t n0 = (size_t)blockIdx.y * 128;
    int nK = K >> 4;

    float acc[4][4][4];
#pragma unroll
    for (int mi = 0; mi < 4; mi++)
#pragma unroll
        for (int ni = 0; ni < 4; ni++)
#pragma unroll
            for (int r = 0; r < 4; r++) acc[mi][ni][r] = 0.0f;

    int lr  = t >> 2;
    int lc4 = (t & 3) * 4;

    auto load_stage = [&](int s, int k0) {
#pragma unroll
        for (int i = 0; i < 2; i++) {
            int r = i * 64 + lr;
            uint32_t da = (uint32_t)__cvta_generic_to_shared(&As[s][r][lc4]);
            CP_ASYNC16(da, &A[(m0 + r) * K + k0 + lc4]);
            uint32_t db = (uint32_t)__cvta_generic_to_shared(&Bs[s][r][lc4]);
            CP_ASYNC16(db, &Bt[(n0 + r) * K + k0 + lc4]);
        }
        CP_COMMIT();
    };

    load_stage(0, 0);
    for (int k0 = 0; k0 < nK; k0++) {
        int s = k0 & 1;
        if (k0 + 1 < nK) { load_stage(s ^ 1, (k0 + 1) << 4); CP_WAIT(1); }
        else             { CP_WAIT(0); }
        __syncthreads();
#pragma unroll
        for (int kk = 0; kk < 16; kk += 8) {
            uint32_t af[4][4], bf[4][2];
#pragma unroll
            for (int mi = 0; mi < 4; mi++) {
                int mr = wm * 64 + mi * 16 + gid;
                af[mi][0] = __float_as_uint(As[s][mr][kk + tig]);
                af[mi][1] = __float_as_uint(As[s][mr + 8][kk + tig]);
                af[mi][2] = __float_as_uint(As[s][mr][kk + tig + 4]);
                af[mi][3] = __float_as_uint(As[s][mr + 8][kk + tig + 4]);
            }
#pragma unroll
            for (int ni = 0; ni < 4; ni++) {
                int nr = wn * 32 + ni * 8 + gid;
                float b0 = Bs[s][nr][kk + tig], b1 = Bs[s][nr][kk + tig + 4];
                if (CVTB) { b0 = to_tf32(b0); b1 = to_tf32(b1); }
                bf[ni][0] = __float_as_uint(b0);
                bf[ni][1] = __float_as_uint(b1);
            }
#pragma unroll
            for (int mi = 0; mi < 4; mi++)
#pragma unroll
                for (int ni = 0; ni < 4; ni++)
                    MMA_TF32(acc[mi][ni][0], acc[mi][ni][1], acc[mi][ni][2], acc[mi][ni][3],
                             af[mi][0], af[mi][1], af[mi][2], af[mi][3],
                             bf[ni][0], bf[ni][1]);
        }
        __syncthreads();
    }

#pragma unroll
    for (int mi = 0; mi < 4; mi++) {
        size_t r0 = m0 + wm * 64 + mi * 16 + gid;
#pragma unroll
        for (int ni = 0; ni < 4; ni++) {
            size_t cb = n0 + wn * 32 + ni * 8 + tig * 2;
            float v0 = acc[mi][ni][0], v1 = acc[mi][ni][1];
            float v2 = acc[mi][ni][2], v3 = acc[mi][ni][3];
            if (CVTC) { v0 = to_tf32(v0); v1 = to_tf32(v1); v2 = to_tf32(v2); v3 = to_tf32(v3); }
            *(float2*)&C[r0 * ldc + cb]       = make_float2(v0, v1);
            *(float2*)&C[(r0 + 8) * ldc + cb] = make_float2(v2, v3);
        }
    }
}

// -------------------- F2: A=g_A2 plain, B gathered from t1T ----------------
// C2[128][32768] ; B row n=(bc,q): k<256 -> t1T[2q][bc*256+k], else Im plane.
__global__ __launch_bounds__(256)
void f2g_tc() {
    __shared__ float As[2][128][20];
    __shared__ float Bs[2][128][20];
    int t = threadIdx.x;
    int warp = t >> 5, lane = t & 31;
    int gid = lane >> 2, tig = lane & 3;
    int wm = warp & 1, wn = warp >> 1;
    size_t n0 = (size_t)blockIdx.x * 128;
    const int K = 512, nK = 32;

    float acc[4][4][4];
#pragma unroll
    for (int mi = 0; mi < 4; mi++)
#pragma unroll
        for (int ni = 0; ni < 4; ni++)
#pragma unroll
            for (int r = 0; r < 4; r++) acc[mi][ni][r] = 0.0f;

    int lr  = t >> 2;
    int lc4 = (t & 3) * 4;

    auto load_stage = [&](int s, int k0) {
#pragma unroll
        for (int i = 0; i < 2; i++) {
            int r = i * 64 + lr;
            uint32_t da = (uint32_t)__cvta_generic_to_shared(&As[s][r][lc4]);
            CP_ASYNC16(da, &g_A2[(size_t)r * K + k0 + lc4]);
            int n = (int)n0 + r;
            int bc = n >> 6, q = n & 63;
            int kg = k0 + lc4;
            int plane = kg >> 8, kk = kg & 255;
            const float* src = g_t1T + (size_t)(2 * q + plane) * ROWS_ + bc * 256 + kk;
            uint32_t db = (uint32_t)__cvta_generic_to_shared(&Bs[s][r][lc4]);
            CP_ASYNC16(db, src);
        }
        CP_COMMIT();
    };

    load_stage(0, 0);
    for (int k0 = 0; k0 < nK; k0++) {
        int s = k0 & 1;
        if (k0 + 1 < nK) { load_stage(s ^ 1, (k0 + 1) << 4); CP_WAIT(1); }
        else             { CP_WAIT(0); }
        __syncthreads();
#pragma unroll
        for (int kk = 0; kk < 16; kk += 8) {
            uint32_t af[4][4], bf[4][2];
#pragma unroll
            for (int mi = 0; mi < 4; mi++) {
                int mr = wm * 64 + mi * 16 + gid;
                af[mi][0] = __float_as_uint(As[s][mr][kk + tig]);
                af[mi][1] = __float_as_uint(As[s][mr + 8][kk + tig]);
                af[mi][2] = __float_as_uint(As[s][mr][kk + tig + 4]);
                af[mi][3] = __float_as_uint(As[s][mr + 8][kk + tig + 4]);
            }
#pragma unroll
            for (int ni = 0; ni < 4; ni++) {
                int nr = wn * 32 + ni * 8 + gid;
                bf[ni][0] = __float_as_uint(Bs[s][nr][kk + tig]);
                bf[ni][1] = __float_as_uint(Bs[s][nr][kk + tig + 4]);
            }
#pragma unroll
            for (int mi = 0; mi < 4; mi++)
#pragma unroll
                for (int ni = 0; ni < 4; ni++)
                    MMA_TF32(acc[mi][ni][0], acc[mi][ni][1], acc[mi][ni][2], acc[mi][ni][3],
                             af[mi][0], af[mi][1], af[mi][2], af[mi][3],
                             bf[ni][0], bf[ni][1]);
        }
        __syncthreads();
    }

#pragma unroll
    for (int mi = 0; mi < 4; mi++) {
        size_t r0 = wm * 64 + mi * 16 + gid;
#pragma unroll
        for (int ni = 0; ni < 4; ni++) {
            size_t cb = n0 + wn * 32 + ni * 8 + tig * 2;
            *(float2*)&g_T2[r0 * 32768 + cb]       = make_float2(acc[mi][ni][0], acc[mi][ni][1]);
            *(float2*)&g_T2[(r0 + 8) * 32768 + cb] = make_float2(acc[mi][ni][2], acc[mi][ni][3]);
        }
    }
}

// -------------------- I2: A gathered from Y2, B=g_CmT2 plain ---------------
// out[131072][256] = gather(Y2) . CmT2^T ; A row m=(bco,h): k<32 -> Y2[2h][bco*32+k]
__global__ __launch_bounds__(256)
void i2g_tc(float* __restrict__ out) {
    const float* Yb = g_Y2 + (size_t)blockIdx.z * 512 * 16384;
    float* C = out + (size_t)blockIdx.z * OUTOFF_;
    __shared__ float As[2][128][20];
    __shared__ float Bs[2][128][20];
    int t = threadIdx.x;
    int warp = t >> 5, lane = t & 31;
    int gid = lane >> 2, tig = lane & 3;
    int wm = warp & 1, wn = warp >> 1;
    size_t m0 = (size_t)blockIdx.x * 128;
    size_t n0 = (size_t)blockIdx.y * 128;
    const int nK = 4;   // K = 64

    float acc[4][4][4];
#pragma unroll
    for (int mi = 0; mi < 4; mi++)
#pragma unroll
        for (int ni = 0; ni < 4; ni++)
#pragma unroll
            for (int r = 0; r < 4; r++) acc[mi][ni][r] = 0.0f;

    int lr  = t >> 2;
    int lc4 = (t & 3) * 4;

    auto load_stage = [&](int s, int k0) {
#pragma unroll
        for (int i = 0; i < 2; i++) {
            int r = i * 64 + lr;
            int m = (int)m0 + r;
            int bco = m >> 8, h = m & 255;
            int kg = k0 + lc4;
            int plane = kg >> 5, kk = kg & 31;
            const float* srca = Yb + (size_t)(2 * h + plane) * 16384 + bco * 32 + kk;
            uint32_t da = (uint32_t)__cvta_generic_to_shared(&As[s][r][lc4]);
            CP_ASYNC16(da, srca);
            uint32_t db = (uint32_t)__cvta_generic_to_shared(&Bs[s][r][lc4]);
            CP_ASYNC16(db, &g_CmT2[(n0 + r) * 64 + k0 + lc4]);
        }
        CP_COMMIT();
    };

    load_stage(0, 0);
    for (int k0 = 0; k0 < nK; k0++) {
        int s = k0 & 1;
        if (k0 + 1 < nK) { load_stage(s ^ 1, (k0 + 1) << 4); CP_WAIT(1); }
        else             { CP_WAIT(0); }
        __syncthreads();
#pragma unroll
        for (int kk = 0; kk < 16; kk += 8) {
            uint32_t af[4][4], bf[4][2];
#pragma unroll
            for (int mi = 0; mi < 4; mi++) {
                int mr = wm * 64 + mi * 16 + gid;
                af[mi][0] = __float_as_uint(As[s][mr][kk + tig]);
                af[mi][1] = __float_as_uint(As[s][mr + 8][kk + tig]);
                af[mi][2] = __float_as_uint(As[s][mr][kk + tig + 4]);
                af[mi][3] = __float_as_uint(As[s][mr + 8][kk + tig + 4]);
            }
#pragma unroll
            for (int ni = 0; ni < 4; ni++) {
                int nr = wn * 32 + ni * 8 + gid;
                bf[ni][0] = __float_as_uint(Bs[s][nr][kk + tig]);
                bf[ni][1] = __float_as_uint(Bs[s][nr][kk + tig + 4]);
            }
#pragma unroll
            for (int mi = 0; mi < 4; mi++)
#pragma unroll
                for (int ni = 0; ni < 4; ni++)
                    MMA_TF32(acc[mi][ni][0], acc[mi][ni][1], acc[mi][ni][2], acc[mi][ni][3],
                             af[mi][0], af[mi][1], af[mi][2], af[mi][3],
                             bf[ni][0], bf[ni][1]);
        }
        __syncthreads();
    }

#pragma unroll
    for (int mi = 0; mi < 4; mi++) {
        size_t r0 = m0 + wm * 64 + mi * 16 + gid;
#pragma unroll
        for (int ni = 0; ni < 4; ni++) {
            size_t cb = n0 + wn * 32 + ni * 8 + tig * 2;
            *(float2*)&C[r0 * 256 + cb]       = make_float2(acc[mi][ni][0], acc[mi][ni][1]);
            *(float2*)&C[(r0 + 8) * 256 + cb] = make_float2(acc[mi][ni][2], acc[mi][ni][3]);
        }
    }
}

// -------------------- channel mix (both branches, fp32) --------------------
// Reads T2 planes; writes S2 in I1 B-operand layout: S2[(bco*32+k2)*128 + {p|64+p}].
__global__ __launch_bounds__(512)
void mix_k(const float* __restrict__ w1r, const float* __restrict__ w1i,
           const float* __restrict__ w2r, const float* __restrict__ w2i,
           const float* __restrict__ w3r, const float* __restrict__ w3i,
           const float* __restrict__ w4r, const float* __restrict__ w4i) {
    int p  = blockIdx.x;
    int zb = blockIdx.y;
    int pm = p & 31;
    const float *wr, *wi;
    if (!zb) { wr = (p < 32) ? w1r : w2r; wi = (p < 32) ? w1i : w2i; }
    else     { wr = (p < 32) ? w3r : w4r; wi = (p < 32) ? w3i : w4i; }
    float* Sout = g_S2 + (size_t)zb * 16384 * 128;

    int t = threadIdx.x;
    int lane = t & 31;
    int warp = t >> 5;
    __shared__ float2 Ts[16][8][32];
    float2 acc[8][4];
#pragma unroll
    for (int b = 0; b < 8; b++)
#pragma unroll
        for (int j = 0; j < 4; j++) acc[b][j] = make_float2(0.f, 0.f);

    for (int cc = 0; cc < 64; cc += 16) {
#pragma unroll
        for (int i = 0; i < 8; i++) {
            int lin = i * 512 + t;
            int ci_l = lin >> 8;
            int b = (lin >> 5) & 7;
            int q = lin & 31;
            int ci = cc + ci_l;
            size_t reidx;
            if (!zb) reidx = (size_t)(2 * p) * 32768 + ((b * 64 + ci) * 64 + q);
            else     reidx = (size_t)(2 * q) * 32768 + ((b * 64 + ci) * 64 + p);
            Ts[ci_l][b][q] = make_float2(g_T2[reidx], g_T2[reidx + 32768]);
        }
        __syncthreads();
        for (int ci_l = 0; ci_l < 16; ci_l++) {
            int ci = cc + ci_l;
            float wr4[4], wi4[4];
#pragma unroll
            for (int j = 0; j < 4; j++) {
                int co = warp * 4 + j;
                size_t off = ((size_t)(ci * 64 + co) * 32 + pm) * 32 + lane;
                wr4[j] = wr[off];
                wi4[j] = wi[off];
            }
#pragma unroll
            for (int b = 0; b < 8; b++) {
                float2 tv = Ts[ci_l][b][lane];
#pragma unroll
                for (int j = 0; j < 4; j++) {
                    acc[b][j].x = fmaf(tv.x, wr4[j], fmaf(-tv.y, wi4[j], acc[b][j].x));
                    acc[b][j].y = fmaf(tv.x, wi4[j], fmaf( tv.y, wr4[j], acc[b][j].y));
                }
            }
        }
        __syncthreads();
    }
#pragma unroll
    for (int b = 0; b < 8; b++)
#pragma unroll
        for (int j = 0; j < 4; j++) {
            int co = warp * 4 + j;
            size_t n = (size_t)(b * 64 + co) * 32 + lane;
            Sout[n * 128 + p]      = to_tf32(acc[b][j].x);
            Sout[n * 128 + 64 + p] = to_tf32(acc[b][j].y);
        }
}

// ------------------------------- launcher ----------------------------------
extern "C" void kernel_launch(void* const* d_in, const int* in_sizes, int n_in,
                              void* d_out, int out_size) {
    const float* x   = (const float*)d_in[0];
    const float* w1r = (const float*)d_in[1];
    const float* w1i = (const float*)d_in[2];
    const float* w2r = (const float*)d_in[3];
    const float* w2i = (const float*)d_in[4];
    const float* w3r = (const float*)d_in[5];
    const float* w3i = (const float*)d_in[6];
    const float* w4r = (const float*)d_in[7];
    const float* w4i = (const float*)d_in[8];
    float* out = (float*)d_out;

    float *pBt, *pA3, *pT1T, *pS2, *pY2;
    cudaGetSymbolAddress((void**)&pBt,  g_Bt);
    cudaGetSymbolAddress((void**)&pA3,  g_A3);
    cudaGetSymbolAddress((void**)&pT1T, g_t1T);
    cudaGetSymbolAddress((void**)&pS2,  g_S2);
    cudaGetSymbolAddress((void**)&pY2,  g_Y2);

    init_tables_k<<<64, 256>>>();

    // F1: t1T[128][131072] = Bt . x^T (x rna-cvt at frag load, out rounded)
    gemm_tc<1, 1><<<dim3(1, 1024), 256>>>(pBt, x, pT1T, 256, ROWS_);

    // F2: T2[128][32768] = A2 . gather(t1T)^T
    f2g_tc<<<256, 256>>>();

    // mix (fp32), writes S2 rounded
    mix_k<<<dim3(64, 2), 512>>>(w1r, w1i, w2r, w2i, w3r, w3i, w4r, w4i);

    // I1: Y2[512][16384] = A3 . S2^T  (per branch, out rounded)
    gemm_tc<0, 1><<<dim3(4, 128), 256>>>(pA3, pS2,               pY2,               128, 16384);
    gemm_tc<0, 1><<<dim3(4, 128), 256>>>(pA3, pS2 + 16384 * 128, pY2 + 512 * 16384, 128, 16384);

    // I2: out = gather(Y2) . CmT2^T  (both branches via grid.z)
    i2g_tc<<<dim3(1024, 2, 2), 256>>>(out);
}

// round 7
// speedup vs baseline: 2.8381x; 1.0884x over previous
#include <cuda_runtime.h>
#include <cstdint>

// ---------------------------------------------------------------------------
// SpectralConv2d (FNO) without FFT: whole pipeline as tf32 mma.sync GEMMs with
// dense (coalesced) operand layouts everywhere.
//   F1 : t1R[bc][q][e][h]      = Bt(128x256) . x^T        (EPI1 relayout)
//   F2 : T2 [2p+e][bc*64+q]    = A2(128x512) . t1R^T      (plain)
//   trz: T2z[2q+e][bc*32+p]    (z-branch mode transpose, p<32)
//   mix: fp32 FFMA, coalesced reads (T2/T2z) and plane-major writes (S2T)
//   trs: S2[n][128] = S2T^T    (I1 B operand)
//   I1 : Y2R[bco*256+h][e*32+k2] = A3(512x128) . S2^T     (EPI2 relayout)
//   I2 : out = Y2R . CmT2^T                                (plain)
// ---------------------------------------------------------------------------

namespace {
constexpr int ROWS_   = 131072;      // B*C*H
constexpr int OUTOFF_ = 33554432;    // B*COUT*H*W
}

// ------------------------- static device scratch ---------------------------
__device__ __align__(16) float g_Bt  [128 * 256];
__device__ __align__(16) float g_A2  [128 * 512];
__device__ __align__(16) float g_A3  [512 * 128];
__device__ __align__(16) float g_CmT2[256 * 64];
__device__ __align__(16) float g_t1R [512 * 32768];      // [bc][q*512+e*256+h] 64MB
__device__ __align__(16) float g_T2  [128 * 32768];      // 16MB
__device__ __align__(16) float g_T2z [128 * 16384];      // 8MB
__device__ __align__(16) float g_S2T [2 * 128 * 16384];  // 16MB (plane-major)
__device__ __align__(16) float g_S2  [2 * 16384 * 128];  // 16MB (row-major, I1 B)
__device__ __align__(16) float g_Y2R [2 * 131072 * 64];  // 67MB

// ------------------------------ helpers ------------------------------------
__device__ __forceinline__ float to_tf32(float x) {
    float r; asm("cvt.rna.tf32.f32 %0, %1;" : "=f"(r) : "f"(x)); return r;
}
#define CP_ASYNC16(dst_u32, src_ptr) \
    asm volatile("cp.async.cg.shared.global [%0], [%1], 16;" :: "r"(dst_u32), "l"(src_ptr))
#define CP_COMMIT() asm volatile("cp.async.commit_group;")
#define CP_WAIT(n)  asm volatile("cp.async.wait_group %0;" :: "n"(n))

#define MMA_TF32(d0,d1,d2,d3, a0,a1,a2,a3, b0,b1)                                   \
    asm volatile("mma.sync.aligned.m16n8k8.row.col.f32.tf32.tf32.f32 "              \
        "{%0,%1,%2,%3}, {%4,%5,%6,%7}, {%8,%9}, {%0,%1,%2,%3};"                     \
        : "+f"(d0), "+f"(d1), "+f"(d2), "+f"(d3)                                    \
        : "r"(a0), "r"(a1), "r"(a2), "r"(a3), "r"(b0), "r"(b1))

// ------------------------------ table init --------------------------------
__global__ void init_tables_k() {
    int t = blockIdx.x * blockDim.x + threadIdx.x;
    if (t >= 64 * 256) return;
    int m = t >> 8, n = t & 255;
    int mf = (m < 32) ? m : m + 192;
    int k = (mf * n) & 255;
    float s, c;
    sincospif((float)k * (1.0f / 128.0f), &s, &c);
    float tc = to_tf32(c), ts = to_tf32(s), tns = to_tf32(-s);

    g_Bt[(2 * m) * 256 + n]     = tc;
    g_Bt[(2 * m + 1) * 256 + n] = tns;
    g_A2[(2 * m) * 512 + n]           = tc;
    g_A2[(2 * m) * 512 + 256 + n]     = ts;
    g_A2[(2 * m + 1) * 512 + n]       = tns;
    g_A2[(2 * m + 1) * 512 + 256 + n] = tc;
    g_A3[(2 * n) * 128 + m]          = tc;
    g_A3[(2 * n) * 128 + 64 + m]     = tns;
    g_A3[(2 * n + 1) * 128 + m]      = ts;
    g_A3[(2 * n + 1) * 128 + 64 + m] = tc;

    int k2 = m & 31;
    int kk = (k2 * n) & 255;
    float s2, c2;
    sincospif((float)kk * (1.0f / 128.0f), &s2, &c2);
    const float sc = 1.0f / 65536.0f;
    float v;
    if (m < 32) v = (k2 == 0) ? sc : 2.0f * sc * c2;
    else        v = (k2 == 0) ? 0.0f : -2.0f * sc * s2;
    g_CmT2[n * 64 + m] = to_tf32(v);
}

// -------------------- tf32 mma.sync GEMM -----------------------------------
// C = A[M,K] * Bt[N,K]^T.  BM=BN=128, BK=16, 8 warps (2x4), 64x32/warp.
// EPI 0: C[r,c] at r*ldc+c.  EPI 1: F1->t1R.  EPI 2: I1->Y2R.
template<int EPI>
__device__ __forceinline__ void epi_store(float* C, size_t r0, size_t cb, int ldc,
                                          float v0, float v1) {
    size_t addr;
    if (EPI == 0)      addr = r0 * (size_t)ldc + cb;
    else if (EPI == 1) addr = (cb >> 8) * 32768 + (r0 >> 1) * 512 + (r0 & 1) * 256 + (cb & 255);
    else               addr = ((cb >> 5) * 256 + (r0 >> 1)) * 64 + (r0 & 1) * 32 + (cb & 31);
    *(float2*)&C[addr] = make_float2(v0, v1);
}

template<int CVTB, int CVTC, int EPI>
__global__ __launch_bounds__(256)
void gemm_tc(const float* __restrict__ A, const float* __restrict__ Bt,
             float* __restrict__ C, int K, int ldc) {
    __shared__ float As[2][128][20];
    __shared__ float Bs[2][128][20];
    int t = threadIdx.x;
    int warp = t >> 5, lane = t & 31;
    int gid = lane >> 2, tig = lane & 3;
    int wm = warp & 1, wn = warp >> 1;
    size_t m0 = (size_t)blockIdx.x * 128;
    size_t n0 = (size_t)blockIdx.y * 128;
    int nK = K >> 4;

    float acc[4][4][4];
#pragma unroll
    for (int mi = 0; mi < 4; mi++)
#pragma unroll
        for (int ni = 0; ni < 4; ni++)
#pragma unroll
            for (int r = 0; r < 4; r++) acc[mi][ni][r] = 0.0f;

    int lr  = t >> 2;
    int lc4 = (t & 3) * 4;

    auto load_stage = [&](int s, int k0) {
#pragma unroll
        for (int i = 0; i < 2; i++) {
            int r = i * 64 + lr;
            uint32_t da = (uint32_t)__cvta_generic_to_shared(&As[s][r][lc4]);
            CP_ASYNC16(da, &A[(m0 + r) * K + k0 + lc4]);
            uint32_t db = (uint32_t)__cvta_generic_to_shared(&Bs[s][r][lc4]);
            CP_ASYNC16(db, &Bt[(n0 + r) * K + k0 + lc4]);
        }
        CP_COMMIT();
    };

    load_stage(0, 0);
    for (int k0 = 0; k0 < nK; k0++) {
        int s = k0 & 1;
        if (k0 + 1 < nK) { load_stage(s ^ 1, (k0 + 1) << 4); CP_WAIT(1); }
        else             { CP_WAIT(0); }
        __syncthreads();
#pragma unroll
        for (int kk = 0; kk < 16; kk += 8) {
            uint32_t af[4][4], bf[4][2];
#pragma unroll
            for (int mi = 0; mi < 4; mi++) {
                int mr = wm * 64 + mi * 16 + gid;
                af[mi][0] = __float_as_uint(As[s][mr][kk + tig]);
                af[mi][1] = __float_as_uint(As[s][mr + 8][kk + tig]);
                af[mi][2] = __float_as_uint(As[s][mr][kk + tig + 4]);
                af[mi][3] = __float_as_uint(As[s][mr + 8][kk + tig + 4]);
            }
#pragma unroll
            for (int ni = 0; ni < 4; ni++) {
                int nr = wn * 32 + ni * 8 + gid;
                float b0 = Bs[s][nr][kk + tig], b1 = Bs[s][nr][kk + tig + 4];
                if (CVTB) { b0 = to_tf32(b0); b1 = to_tf32(b1); }
                bf[ni][0] = __float_as_uint(b0);
                bf[ni][1] = __float_as_uint(b1);
            }
#pragma unroll
            for (int mi = 0; mi < 4; mi++)
#pragma unroll
                for (int ni = 0; ni < 4; ni++)
                    MMA_TF32(acc[mi][ni][0], acc[mi][ni][1], acc[mi][ni][2], acc[mi][ni][3],
                             af[mi][0], af[mi][1], af[mi][2], af[mi][3],
                             bf[ni][0], bf[ni][1]);
        }
        __syncthreads();
    }

#pragma unroll
    for (int mi = 0; mi < 4; mi++) {
        size_t r0 = m0 + wm * 64 + mi * 16 + gid;
#pragma unroll
        for (int ni = 0; ni < 4; ni++) {
            size_t cb = n0 + wn * 32 + ni * 8 + tig * 2;
            float v0 = acc[mi][ni][0], v1 = acc[mi][ni][1];
            float v2 = acc[mi][ni][2], v3 = acc[mi][ni][3];
            if (CVTC) { v0 = to_tf32(v0); v1 = to_tf32(v1); v2 = to_tf32(v2); v3 = to_tf32(v3); }
            epi_store<EPI>(C, r0,     cb, ldc, v0, v1);
            epi_store<EPI>(C, r0 + 8, cb, ldc, v2, v3);
        }
    }
}

// ------------- T2 -> T2z: z-branch mode transpose (p<32, q<64) -------------
__global__ __launch_bounds__(256)
void tr_z_k() {
    __shared__ float tile[2][32][65];
    int bc = blockIdx.x;
    int t = threadIdx.x;
#pragma unroll
    for (int i = 0; i < 16; i++) {
        int lin = i * 256 + t;
        int e = lin >> 11, rem = lin & 2047;
        int p = rem >> 6, q = rem & 63;
        tile[e][p][q] = g_T2[(size_t)(2 * p + e) * 32768 + bc * 64 + q];
    }
    __syncthreads();
#pragma unroll
    for (int i = 0; i < 16; i++) {
        int lin = i * 256 + t;
        int e = lin >> 11, rem = lin & 2047;
        int q = rem >> 5, p = rem & 31;
        g_T2z[(size_t)(2 * q + e) * 16384 + bc * 32 + p] = tile[e][p][q];
    }
}

// ----------------- S2T (plane-major) -> S2 (row-major, I1 B) ---------------
__global__ void tr_s_k() {
    __shared__ float tile[32][33];
    int zb = blockIdx.z;
    int n0 = blockIdx.x * 32, p0 = blockIdx.y * 32;
    const float* src = g_S2T + (size_t)zb * 128 * 16384;
    float* dst = g_S2 + (size_t)zb * 16384 * 128;
    int tx = threadIdx.x, ty = threadIdx.y;
#pragma unroll
    for (int k = 0; k < 32; k += 8)
        tile[ty + k][tx] = src[(size_t)(p0 + ty + k) * 16384 + n0 + tx];
    __syncthreads();
#pragma unroll
    for (int k = 0; k < 32; k += 8)
        dst[(size_t)(n0 + ty + k) * 128 + p0 + tx] = tile[tx][ty + k];
}

// -------------------- channel mix (both branches, fp32) --------------------
// x: reads T2[2p][bc*64+q] ; z: reads T2z[2p][bc*32+q]  (both coalesced)
// writes plane-major S2T[{p|64+p}][n],  n = (b*64+co)*32+k2  (coalesced)
__global__ __launch_bounds__(512)
void mix_k(const float* __restrict__ w1r, const float* __restrict__ w1i,
           const float* __restrict__ w2r, const float* __restrict__ w2i,
           const float* __restrict__ w3r, const float* __restrict__ w3i,
           const float* __restrict__ w4r, const float* __restrict__ w4i) {
    int p  = blockIdx.x;
    int zb = blockIdx.y;
    int pm = p & 31;
    const float *wr, *wi;
    if (!zb) { wr = (p < 32) ? w1r : w2r; wi = (p < 32) ? w1i : w2i; }
    else     { wr = (p < 32) ? w3r : w4r; wi = (p < 32) ? w3i : w4i; }
    float* Sout = g_S2T + (size_t)zb * 128 * 16384;

    int t = threadIdx.x;
    int lane = t & 31;
    int warp = t >> 5;
    __shared__ float2 Ts[16][8][32];
    float2 acc[8][4];
#pragma unroll
    for (int b = 0; b < 8; b++)
#pragma unroll
        for (int j = 0; j < 4; j++) acc[b][j] = make_float2(0.f, 0.f);

    for (int cc = 0; cc < 64; cc += 16) {
#pragma unroll
        for (int i = 0; i < 8; i++) {
            int lin = i * 512 + t;
            int ci_l = lin >> 8;
            int b = (lin >> 5) & 7;
            int q = lin & 31;
            int ci = cc + ci_l;
            float re, im;
            if (!zb) {
                size_t ix = (size_t)(2 * p) * 32768 + ((b * 64 + ci) * 64 + q);
                re = g_T2[ix]; im = g_T2[ix + 32768];
            } else {
                size_t ix = (size_t)(2 * p) * 16384 + ((b * 64 + ci) * 32 + q);
                re = g_T2z[ix]; im = g_T2z[ix + 16384];
            }
            Ts[ci_l][b][q] = make_float2(re, im);
        }
        __syncthreads();
        for (int ci_l = 0; ci_l < 16; ci_l++) {
            int ci = cc + ci_l;
            float wr4[4], wi4[4];
#pragma unroll
            for (int j = 0; j < 4; j++) {
                int co = warp * 4 + j;
                size_t off = ((size_t)(ci * 64 + co) * 32 + pm) * 32 + lane;
                wr4[j] = wr[off];
                wi4[j] = wi[off];
            }
#pragma unroll
            for (int b = 0; b < 8; b++) {
                float2 tv = Ts[ci_l][b][lane];
#pragma unroll
                for (int j = 0; j < 4; j++) {
                    acc[b][j].x = fmaf(tv.x, wr4[j], fmaf(-tv.y, wi4[j], acc[b][j].x));
                    acc[b][j].y = fmaf(tv.x, wi4[j], fmaf( tv.y, wr4[j], acc[b][j].y));
                }
            }
        }
        __syncthreads();
    }
#pragma unroll
    for (int b = 0; b < 8; b++)
#pragma unroll
        for (int j = 0; j < 4; j++) {
            int co = warp * 4 + j;
            size_t n = (size_t)(b * 64 + co) * 32 + lane;
            Sout[(size_t)p * 16384 + n]        = to_tf32(acc[b][j].x);
            Sout[(size_t)(64 + p) * 16384 + n] = to_tf32(acc[b][j].y);
        }
}

// ------------------------------- launcher ----------------------------------
extern "C" void kernel_launch(void* const* d_in, const int* in_sizes, int n_in,
                              void* d_out, int out_size) {
    const float* x   = (const float*)d_in[0];
    const float* w1r = (const float*)d_in[1];
    const float* w1i = (const float*)d_in[2];
    const float* w2r = (const float*)d_in[3];
    const float* w2i = (const float*)d_in[4];
    const float* w3r = (const float*)d_in[5];
    const float* w3i = (const float*)d_in[6];
    const float* w4r = (const float*)d_in[7];
    const float* w4i = (const float*)d_in[8];
    float* out = (float*)d_out;

    float *pBt, *pA2, *pA3, *pCmT2, *pT1R, *pT2, *pS2, *pY2R;
    cudaGetSymbolAddress((void**)&pBt,   g_Bt);
    cudaGetSymbolAddress((void**)&pA2,   g_A2);
    cudaGetSymbolAddress((void**)&pA3,   g_A3);
    cudaGetSymbolAddress((void**)&pCmT2, g_CmT2);
    cudaGetSymbolAddress((void**)&pT1R,  g_t1R);
    cudaGetSymbolAddress((void**)&pT2,   g_T2);
    cudaGetSymbolAddress((void**)&pS2,   g_S2);
    cudaGetSymbolAddress((void**)&pY2R,  g_Y2R);

    init_tables_k<<<64, 256>>>();

    // F1: t1R = Bt . x^T   (M=128, N=131072, K=256)
    gemm_tc<1, 1, 1><<<dim3(1, 1024), 256>>>(pBt, x, pT1R, 256, 0);

    // F2: T2 = A2 . t1R^T  (M=128, N=32768, K=512)
    gemm_tc<0, 0, 0><<<dim3(1, 256), 256>>>(pA2, pT1R, pT2, 512, 32768);

    // z-branch mode transpose
    tr_z_k<<<512, 256>>>();

    // channel mix (fp32), writes plane-major S2T (rounded)
    mix_k<<<dim3(64, 2), 512>>>(w1r, w1i, w2r, w2i, w3r, w3i, w4r, w4i);

    // S2T -> S2 row-major
    tr_s_k<<<dim3(512, 4, 2), dim3(32, 8)>>>();

    // I1: Y2R = A3 . S2^T  (M=512, N=16384, K=128), per branch
    gemm_tc<0, 1, 2><<<dim3(4, 128), 256>>>(pA3, pS2,               pY2R,                128, 0);
    gemm_tc<0, 1, 2><<<dim3(4, 128), 256>>>(pA3, pS2 + 16384 * 128, pY2R + 131072 * 64,  128, 0);

    // I2: out = Y2R . CmT2^T (M=131072, N=256, K=64), per branch
    gemm_tc<0, 0, 0><<<dim3(1024, 2), 256>>>(pY2R,               pCmT2, out,           64, 256);
    gemm_tc<0, 0, 0><<<dim3(1024, 2), 256>>>(pY2R + 131072 * 64, pCmT2, out + OUTOFF_, 64, 256);
}